// round 11
// baseline (speedup 1.0000x reference)
#include <cuda_runtime.h>
#include <cuda_bf16.h>
#include <cstdint>

// VSC3x3Rulebook on GB300 — HMMA bf16-split, cp.async-staged gather,
// TMA bulk-reduce scatter. r6 shape (TILE_E=128, 2 CTA/SM) + async gather.
//   out = scatter_add_{k,m}( feats[in_rows[k,m]] @ weight[k] -> out_rows[k,m] ) + bias
//   d_out (float32): [ float(coords) | out[N,64] ]

#define TILE_E 128
#define GRID_X 32

// XOR swizzle on 128B-stride tiles (SW128 pattern)
#define SW(o) ((o) ^ (((o) >> 3) & 0x70))

// smem layout from 1024-aligned base
#define WLO_OFF 0          // 64 x 128B  bf16 W_lo [co][ci], swizzled
#define AHI_OFF 8192       // 128 x 128B bf16 A_hi, swizzled
#define ALO_OFF 24576      // 128 x 128B bf16 A_lo, swizzled
#define FIN_OFF 40960      // 128 x 272B f32 gathered rows (cp.async dst)
#define STG_OFF 75776      // 128 x 272B f32 D stage
#define SMEM_SZ (110592 + 1024)

// ---- merged prep: bias-init of out + coords int->float cast ----
__global__ void vsc_prep(float4* __restrict__ out4,
                         const float4* __restrict__ bias4, int total4,
                         const int4* __restrict__ coords4,
                         float4* __restrict__ outc4, int nc4) {
    int idx = blockIdx.x * blockDim.x + threadIdx.x;
    if (idx < total4) {
        out4[idx] = bias4[idx & 15];
    } else {
        int j = idx - total4;
        if (j < nc4) {
            int4 v = coords4[j];
            outc4[j] = make_float4((float)v.x, (float)v.y, (float)v.z, (float)v.w);
        }
    }
}

__device__ __forceinline__ uint2 bf16split2(float a, float b) {
    __nv_bfloat16 ha = __float2bfloat16(a);
    __nv_bfloat16 hb = __float2bfloat16(b);
    __nv_bfloat16 la = __float2bfloat16(a - __bfloat162float(ha));
    __nv_bfloat16 lb = __float2bfloat16(b - __bfloat162float(hb));
    uint2 r;
    r.x = (uint32_t)__bfloat16_as_ushort(ha) | ((uint32_t)__bfloat16_as_ushort(hb) << 16);
    r.y = (uint32_t)__bfloat16_as_ushort(la) | ((uint32_t)__bfloat16_as_ushort(lb) << 16);
    return r;
}

__device__ __forceinline__ void mma16816(float* c, const uint32_t* a,
                                         uint32_t b0, uint32_t b1) {
    asm volatile(
        "mma.sync.aligned.m16n8k16.row.col.f32.bf16.bf16.f32 "
        "{%0,%1,%2,%3}, {%4,%5,%6,%7}, {%8,%9}, {%0,%1,%2,%3};"
        : "+f"(c[0]), "+f"(c[1]), "+f"(c[2]), "+f"(c[3])
        : "r"(a[0]), "r"(a[1]), "r"(a[2]), "r"(a[3]), "r"(b0), "r"(b1));
}

#define LDMX4(r, addr)                                                     \
    asm volatile("ldmatrix.sync.aligned.m8n8.x4.shared.b16 "               \
                 "{%0,%1,%2,%3}, [%4];"                                    \
                 : "=r"((r)[0]), "=r"((r)[1]), "=r"((r)[2]), "=r"((r)[3])  \
                 : "r"(addr))
#define LDMX2(r0, r1, addr)                                                \
    asm volatile("ldmatrix.sync.aligned.m8n8.x2.shared.b16 "               \
                 "{%0,%1}, [%2];"                                          \
                 : "=r"(r0), "=r"(r1) : "r"(addr))

#define CP16(saddr, gaddr)                                                 \
    asm volatile("cp.async.cg.shared.global [%0], [%1], 16;"               \
                 :: "r"(saddr), "l"(gaddr) : "memory")

// convert one entry slice (entry e, ci octet g8) from f32 pair to bf16 tiles
__device__ __forceinline__ void sts_pass(char* smem, int e, int g8,
                                         const float4 v0, const float4 v1) {
    const uint2 p0 = bf16split2(v0.x, v0.y);
    const uint2 p1 = bf16split2(v0.z, v0.w);
    const uint2 p2 = bf16split2(v1.x, v1.y);
    const uint2 p3 = bf16split2(v1.z, v1.w);
    const unsigned off = (unsigned)e * 128 + (unsigned)g8 * 16;
    const unsigned sw  = SW(off);
    *reinterpret_cast<uint4*>(smem + AHI_OFF + sw) = make_uint4(p0.x, p1.x, p2.x, p3.x);
    *reinterpret_cast<uint4*>(smem + ALO_OFF + sw) = make_uint4(p0.y, p1.y, p2.y, p3.y);
}

__global__ __launch_bounds__(256, 2) void vsc_mma(
    const float* __restrict__ feats,
    const int*   __restrict__ in_rows,
    const int*   __restrict__ out_rows,
    const float* __restrict__ weight,
    float*       __restrict__ out,
    int M, int ntiles)
{
    extern __shared__ __align__(16) char dsm[];
    const uint32_t raw = (uint32_t)__cvta_generic_to_shared(dsm);
    const uint32_t sb  = (raw + 1023u) & ~1023u;
    char* smem = dsm + (sb - raw);

    const int tid   = threadIdx.x;
    const int w     = tid >> 5;
    const int l     = tid & 31;
    const int eslab = w >> 1;    // 0..3 : 32-entry slab
    const int nhalf = w & 1;     // 0/1  : output-column half
    const int k     = blockIdx.y;
    const long kM   = (long)k * M;
    const float* Wg = weight + (size_t)k * 4096;   // [ci][co]

    // ---- W_lo -> smem [co][ci], 128B rows, swizzled ----
    for (int i = tid; i < 4096; i += 256) {
        const int n = i >> 6, ci = i & 63;
        const float v = Wg[(size_t)ci * 64 + n];
        const float lo = v - __bfloat162float(__float2bfloat16(v));
        const unsigned sw = SW((unsigned)n * 128 + (unsigned)ci * 2);
        *reinterpret_cast<__nv_bfloat16*>(smem + WLO_OFF + sw) = __float2bfloat16(lo);
    }

    // ---- W_hi fragments -> registers (32 regs) ----
    uint32_t Bhi[4][4][2];
    {
        const int n = nhalf * 32 + (l >> 2);
        #pragma unroll
        for (int nt = 0; nt < 4; nt++)
            #pragma unroll
            for (int ks = 0; ks < 4; ks++)
                #pragma unroll
                for (int j = 0; j < 2; j++) {
                    const int ci0 = ks * 16 + j * 8 + 2 * (l & 3);
                    const float w0 = Wg[(size_t)ci0 * 64 + n + nt * 8];
                    const float w1 = Wg[(size_t)(ci0 + 1) * 64 + n + nt * 8];
                    Bhi[nt][ks][j] =
                        (uint32_t)__bfloat16_as_ushort(__float2bfloat16(w0))
                      | ((uint32_t)__bfloat16_as_ushort(__float2bfloat16(w1)) << 16);
                }
    }

    // ldmatrix lane-address components (tile-invariant)
    const uint32_t a_row = (l & 7) + ((l >> 3) & 1) * 8;   // + eslab*32 + s*16
    const uint32_t a_kof = ((l >> 4) & 1) * 16;            // bytes
    const uint32_t b_row = nhalf * 32 + (l & 7);
    const uint32_t b_kof = ((l >> 3) & 1) * 16;            // bytes

    const int er = tid >> 3;   // gather entry-in-pass 0..31
    const int g8 = tid & 7;    // ci octet

    // ---- prologue: async-gather first tile's f32 rows into FIN ----
    {
        const int ebase = blockIdx.x * TILE_E;
        #pragma unroll
        for (int p = 0; p < 4; p++) {
            const int e = p * 32 + er;
            int eg = ebase + e;
            if (eg >= M) eg = M - 1;
            const int irow = __ldg(in_rows + kM + eg);
            const char* g = reinterpret_cast<const char*>(
                feats + (size_t)irow * 64 + g8 * 8);
            const uint32_t s = sb + FIN_OFF + e * 272 + g8 * 32;
            CP16(s, g);
            CP16(s + 16, g + 16);
        }
    }
    asm volatile("cp.async.commit_group;" ::: "memory");

    for (int tile = blockIdx.x; tile < ntiles; tile += GRID_X) {
        const int ebase = tile * TILE_E;
        const bool havenext = (tile + GRID_X) < ntiles;
        const int nbase = ebase + GRID_X * TILE_E;

        // ---- current tile's gathered rows are in FIN ----
        asm volatile("cp.async.wait_group 0;" ::: "memory");
        __syncthreads();

        // prefetch next tile's indices while convert runs (short-lived regs)
        int irw[4];
        if (havenext) {
            #pragma unroll
            for (int p = 0; p < 4; p++) {
                int eg = nbase + p * 32 + er;
                if (eg >= M) eg = M - 1;
                irw[p] = __ldg(in_rows + kM + eg);
            }
        }
        int orw = -1;
        if (tid < TILE_E) {
            const int eg = ebase + tid;
            if (eg < M) orw = __ldg(out_rows + kM + eg);
        }

        // ---- convert FIN (f32) -> A_hi/A_lo bf16 tiles (all smem-local) ----
        #pragma unroll
        for (int p = 0; p < 4; p++) {
            const int e = p * 32 + er;
            const float4* f = reinterpret_cast<const float4*>(
                smem + FIN_OFF + e * 272 + g8 * 32);
            sts_pass(smem, e, g8, f[0], f[1]);
        }
        __syncthreads();   // A tiles ready; FIN fully drained

        // ---- issue next tile's gather (fire-and-forget, overlaps MMA) ----
        if (havenext) {
            #pragma unroll
            for (int p = 0; p < 4; p++) {
                const int e = p * 32 + er;
                const char* g = reinterpret_cast<const char*>(
                    feats + (size_t)irw[p] * 64 + g8 * 8);
                const uint32_t s = sb + FIN_OFF + e * 272 + g8 * 32;
                CP16(s, g);
                CP16(s + 16, g + 16);
            }
        }
        asm volatile("cp.async.commit_group;" ::: "memory");

        // ---- compute: 32 entries x 32 cols per warp ----
        float acc[2][4][4];
        #pragma unroll
        for (int s = 0; s < 2; s++)
            #pragma unroll
            for (int nt = 0; nt < 4; nt++)
                #pragma unroll
                for (int r = 0; r < 4; r++) acc[s][nt][r] = 0.f;

        #pragma unroll
        for (int ks = 0; ks < 4; ks++) {
            uint32_t blo[4][2];
            #pragma unroll
            for (int nt = 0; nt < 4; nt++) {
                const unsigned bo = (b_row + nt * 8) * 128 + ks * 32 + b_kof;
                LDMX2(blo[nt][0], blo[nt][1], sb + WLO_OFF + SW(bo));
            }
            #pragma unroll
            for (int s = 0; s < 2; s++) {
                const unsigned ao =
                    (eslab * 32 + s * 16 + a_row) * 128 + ks * 32 + a_kof;
                const unsigned aosw = SW(ao);
                uint32_t ahi[4], alo[4];
                LDMX4(ahi, sb + AHI_OFF + aosw);
                LDMX4(alo, sb + ALO_OFF + aosw);
                #pragma unroll
                for (int nt = 0; nt < 4; nt++) {
                    mma16816(acc[s][nt], ahi, Bhi[nt][ks][0], Bhi[nt][ks][1]);
                    mma16816(acc[s][nt], ahi, blo[nt][0],     blo[nt][1]);
                    mma16816(acc[s][nt], alo, Bhi[nt][ks][0], Bhi[nt][ks][1]);
                }
            }
        }

        // ---- epilogue ----
        asm volatile("cp.async.bulk.wait_group.read 0;" ::: "memory");
        __syncthreads();   // D stage free; all ldmatrix done

        {
            const int r0 = l >> 2;            // 0..7
            const int cb = 2 * (l & 3);       // 0,2,4,6
            float* stg = reinterpret_cast<float*>(smem + STG_OFF);
            #pragma unroll
            for (int s = 0; s < 2; s++) {
                const int eb = eslab * 32 + s * 16;
                #pragma unroll
                for (int nt = 0; nt < 4; nt++) {
                    const int c = nhalf * 32 + nt * 8 + cb;
                    *reinterpret_cast<float2*>(&stg[(eb + r0) * 68 + c]) =
                        make_float2(acc[s][nt][0], acc[s][nt][1]);
                    *reinterpret_cast<float2*>(&stg[(eb + r0 + 8) * 68 + c]) =
                        make_float2(acc[s][nt][2], acc[s][nt][3]);
                }
            }
        }
        asm volatile("fence.proxy.async.shared::cta;" ::: "memory");
        __syncthreads();

        if (orw >= 0) {
            const float* dst = out + (size_t)orw * 64;
            const uint32_t src = sb + STG_OFF + tid * 272;
            asm volatile(
                "cp.reduce.async.bulk.global.shared::cta.bulk_group.add.f32 "
                "[%0], [%1], 256;"
                :: "l"(dst), "r"(src) : "memory");
        }
        asm volatile("cp.async.bulk.commit_group;" ::: "memory");
    }

    asm volatile("cp.async.bulk.wait_group 0;" ::: "memory");
}

extern "C" void kernel_launch(void* const* d_in, const int* in_sizes, int n_in,
                              void* d_out, int out_size) {
    const int*   coords   = (const int*)  d_in[0];
    const float* feats    = (const float*)d_in[1];
    const int*   in_rows  = (const int*)  d_in[2];
    const int*   out_rows = (const int*)  d_in[3];
    const float* weight   = (const float*)d_in[4];
    const float* bias     = (const float*)d_in[5];

    const int N = in_sizes[1] / 64;   // feats is [N, 64]
    const int M = in_sizes[2] / 9;    // in_rows is [9, M]

    // d_out is float32: [ float(coords) | out[N,64] ]
    float* outf = (float*)d_out;
    long coords_elems = (long)out_size - (long)N * 64;
    if (coords_elems < 0) coords_elems = 0;
    if (coords_elems > in_sizes[0]) coords_elems = in_sizes[0];
    float* out = outf + coords_elems;

    const int total4 = N * 16;
    const int nc4    = (int)(coords_elems / 4);
    const int tot    = total4 + nc4;
    vsc_prep<<<(tot + 255) / 256, 256>>>(
        (float4*)out, (const float4*)bias, total4,
        (const int4*)coords, (float4*)outf, nc4);

    cudaFuncSetAttribute(vsc_mma, cudaFuncAttributeMaxDynamicSharedMemorySize,
                         SMEM_SZ);
    const int ntiles = (M + TILE_E - 1) / TILE_E;
    dim3 grid(GRID_X, 9);
    vsc_mma<<<grid, 256, SMEM_SZ>>>(feats, in_rows, out_rows, weight, out,
                                    M, ntiles);
}

// round 12
// speedup vs baseline: 1.2250x; 1.2250x over previous
#include <cuda_runtime.h>
#include <cuda_bf16.h>
#include <cstdint>

// VSC3x3Rulebook on GB300 — HMMA bf16-split + TMA bulk-reduce scatter.
// Round-6 configuration (measured best) + read-scoped drain + merged prep.
//   out = scatter_add_{k,m}( feats[in_rows[k,m]] @ weight[k] -> out_rows[k,m] ) + bias
//   d_out (float32): [ float(coords) | out[N,64] ]

#define TILE_E 128
#define GRID_X 32

// dynamic smem layout (16B aligned base; all offsets 16B multiples)
#define WLO_OFF 0          // 64 x 144B  : bf16 W_lo, [co][ci]
#define AHI_OFF 9216       // 128 x 144B : bf16 A_hi
#define ALO_OFF 27648      // 128 x 144B : bf16 A_lo
#define STG_OFF 46080      // 128 x 288B : f32 D stage (72-float stride)
#define SMEM_SZ 82944

// ---- merged prep: bias-init of out + coords int->float cast ----
__global__ void vsc_prep(float4* __restrict__ out4,
                         const float4* __restrict__ bias4, int total4,
                         const int4* __restrict__ coords4,
                         float4* __restrict__ outc4, int nc4) {
    int idx = blockIdx.x * blockDim.x + threadIdx.x;
    if (idx < total4) {
        out4[idx] = bias4[idx & 15];
    } else {
        int j = idx - total4;
        if (j < nc4) {
            int4 v = coords4[j];
            outc4[j] = make_float4((float)v.x, (float)v.y, (float)v.z, (float)v.w);
        }
    }
}

__device__ __forceinline__ uint2 bf16split2(float a, float b) {
    __nv_bfloat16 ha = __float2bfloat16(a);
    __nv_bfloat16 hb = __float2bfloat16(b);
    __nv_bfloat16 la = __float2bfloat16(a - __bfloat162float(ha));
    __nv_bfloat16 lb = __float2bfloat16(b - __bfloat162float(hb));
    uint2 r;
    r.x = (uint32_t)__bfloat16_as_ushort(ha) | ((uint32_t)__bfloat16_as_ushort(hb) << 16);
    r.y = (uint32_t)__bfloat16_as_ushort(la) | ((uint32_t)__bfloat16_as_ushort(lb) << 16);
    return r;
}

__device__ __forceinline__ void mma16816(float* c, const uint32_t* a,
                                         uint32_t b0, uint32_t b1) {
    asm volatile(
        "mma.sync.aligned.m16n8k16.row.col.f32.bf16.bf16.f32 "
        "{%0,%1,%2,%3}, {%4,%5,%6,%7}, {%8,%9}, {%0,%1,%2,%3};"
        : "+f"(c[0]), "+f"(c[1]), "+f"(c[2]), "+f"(c[3])
        : "r"(a[0]), "r"(a[1]), "r"(a[2]), "r"(a[3]), "r"(b0), "r"(b1));
}

#define LDMX4(r, addr)                                                     \
    asm volatile("ldmatrix.sync.aligned.m8n8.x4.shared.b16 "               \
                 "{%0,%1,%2,%3}, [%4];"                                    \
                 : "=r"((r)[0]), "=r"((r)[1]), "=r"((r)[2]), "=r"((r)[3])  \
                 : "r"(addr))
#define LDMX2(r0, r1, addr)                                                \
    asm volatile("ldmatrix.sync.aligned.m8n8.x2.shared.b16 "               \
                 "{%0,%1}, [%2];"                                          \
                 : "=r"(r0), "=r"(r1) : "r"(addr))

__global__ __launch_bounds__(256, 2) void vsc_mma(
    const float* __restrict__ feats,
    const int*   __restrict__ in_rows,
    const int*   __restrict__ out_rows,
    const float* __restrict__ weight,
    float*       __restrict__ out,
    int M, int ntiles)
{
    extern __shared__ __align__(16) char smem[];
    const uint32_t sb = (uint32_t)__cvta_generic_to_shared(smem);

    const int tid   = threadIdx.x;
    const int w     = tid >> 5;
    const int l     = tid & 31;
    const int eslab = w >> 1;    // 0..3 : 32-entry slab
    const int nhalf = w & 1;     // 0/1  : output-column half
    const int k     = blockIdx.y;
    const long kM   = (long)k * M;
    const float* Wg = weight + (size_t)k * 4096;   // [ci][co]

    // ---- W_lo -> smem [co][ci], 144B rows ----
    for (int i = tid; i < 4096; i += 256) {
        const int n = i >> 6, ci = i & 63;
        const float v = Wg[(size_t)ci * 64 + n];
        const float lo = v - __bfloat162float(__float2bfloat16(v));
        *reinterpret_cast<__nv_bfloat16*>(smem + WLO_OFF + n * 144 + ci * 2) =
            __float2bfloat16(lo);
    }

    // ---- W_hi fragments -> registers ----
    uint32_t Bhi[4][4][2];
    {
        const int n = nhalf * 32 + (l >> 2);
        #pragma unroll
        for (int nt = 0; nt < 4; nt++)
            #pragma unroll
            for (int ks = 0; ks < 4; ks++)
                #pragma unroll
                for (int j = 0; j < 2; j++) {
                    const int ci0 = ks * 16 + j * 8 + 2 * (l & 3);
                    const float w0 = Wg[(size_t)ci0 * 64 + n + nt * 8];
                    const float w1 = Wg[(size_t)(ci0 + 1) * 64 + n + nt * 8];
                    Bhi[nt][ks][j] =
                        (uint32_t)__bfloat16_as_ushort(__float2bfloat16(w0))
                      | ((uint32_t)__bfloat16_as_ushort(__float2bfloat16(w1)) << 16);
                }
    }
    __syncthreads();

    const uint32_t a_row = (l & 7) + ((l >> 3) & 1) * 8;
    const uint32_t a_kof = (l >> 4) * 8;
    const uint32_t b_row = nhalf * 32 + (l & 7);
    const uint32_t b_kof = ((l >> 3) & 1) * 8;

    const int er = tid >> 3;
    const int g8 = tid & 7;

    for (int tile = blockIdx.x; tile < ntiles; tile += GRID_X) {
        const int ebase = tile * TILE_E;

        // ---- gather + split + STS (A buffers; stage untouched) ----
        #pragma unroll
        for (int p = 0; p < 4; p++) {
            const int e = p * 32 + er;
            int eg = ebase + e;
            if (eg >= M) eg = M - 1;
            const int irow = __ldg(in_rows + kM + eg);
            const float4* fp = reinterpret_cast<const float4*>(
                feats + (size_t)irow * 64 + g8 * 8);
            const float4 v0 = __ldg(fp);
            const float4 v1 = __ldg(fp + 1);
            const uint2 p0 = bf16split2(v0.x, v0.y);
            const uint2 p1 = bf16split2(v0.z, v0.w);
            const uint2 p2 = bf16split2(v1.x, v1.y);
            const uint2 p3 = bf16split2(v1.z, v1.w);
            const int off = e * 144 + g8 * 16;
            *reinterpret_cast<uint4*>(smem + AHI_OFF + off) =
                make_uint4(p0.x, p1.x, p2.x, p3.x);
            *reinterpret_cast<uint4*>(smem + ALO_OFF + off) =
                make_uint4(p0.y, p1.y, p2.y, p3.y);
        }
        __syncthreads();

        // ---- compute ----
        float acc[2][4][4];
        #pragma unroll
        for (int s = 0; s < 2; s++)
            #pragma unroll
            for (int nt = 0; nt < 4; nt++)
                #pragma unroll
                for (int r = 0; r < 4; r++) acc[s][nt][r] = 0.f;

        #pragma unroll
        for (int ks = 0; ks < 4; ks++) {
            uint32_t blo[4][2];
            #pragma unroll
            for (int nt = 0; nt < 4; nt++) {
                const uint32_t ba = sb + WLO_OFF
                    + (b_row + nt * 8) * 144 + (ks * 16 + b_kof) * 2;
                LDMX2(blo[nt][0], blo[nt][1], ba);
            }
            #pragma unroll
            for (int s = 0; s < 2; s++) {
                const uint32_t ao =
                    (eslab * 32 + s * 16 + a_row) * 144 + (ks * 16 + a_kof) * 2;
                uint32_t ahi[4], alo[4];
                LDMX4(ahi, sb + AHI_OFF + ao);
                LDMX4(alo, sb + ALO_OFF + ao);
                #pragma unroll
                for (int nt = 0; nt < 4; nt++) {
                    mma16816(acc[s][nt], ahi, Bhi[nt][ks][0], Bhi[nt][ks][1]);
                    mma16816(acc[s][nt], ahi, blo[nt][0],     blo[nt][1]);
                    mma16816(acc[s][nt], alo, Bhi[nt][ks][0], Bhi[nt][ks][1]);
                }
            }
        }

        // ---- drain previous tile's bulk reduces (reads only), restage ----
        asm volatile("cp.async.bulk.wait_group.read 0;" ::: "memory");
        __syncthreads();   // stage free; also all warps past ldmatrix

        {
            const int r0 = l >> 2;            // 0..7
            const int cb = 2 * (l & 3);       // 0,2,4,6
            #pragma unroll
            for (int s = 0; s < 2; s++) {
                const int eb = eslab * 32 + s * 16;
                float* stg = reinterpret_cast<float*>(smem + STG_OFF);
                #pragma unroll
                for (int nt = 0; nt < 4; nt++) {
                    const int c = nhalf * 32 + nt * 8 + cb;
                    *reinterpret_cast<float2*>(&stg[(eb + r0) * 72 + c]) =
                        make_float2(acc[s][nt][0], acc[s][nt][1]);
                    *reinterpret_cast<float2*>(&stg[(eb + r0 + 8) * 72 + c]) =
                        make_float2(acc[s][nt][2], acc[s][nt][3]);
                }
            }
        }
        asm volatile("fence.proxy.async.shared::cta;" ::: "memory");
        __syncthreads();

        // ---- one 256B bulk reduce-add per entry ----
        if (tid < TILE_E) {
            const int eg = ebase + tid;
            if (eg < M) {
                const int orow = __ldg(out_rows + kM + eg);
                const float* dst = out + (size_t)orow * 64;
                const uint32_t src = sb + STG_OFF + tid * 288;
                asm volatile(
                    "cp.reduce.async.bulk.global.shared::cta.bulk_group.add.f32 "
                    "[%0], [%1], 256;"
                    :: "l"(dst), "r"(src) : "memory");
            }
        }
        asm volatile("cp.async.bulk.commit_group;" ::: "memory");
        // no sync: next gather writes A buffers only; stage protected by
        // wait_group.read + sync at the top of the next epilogue.
    }

    asm volatile("cp.async.bulk.wait_group 0;" ::: "memory");
}

extern "C" void kernel_launch(void* const* d_in, const int* in_sizes, int n_in,
                              void* d_out, int out_size) {
    const int*   coords   = (const int*)  d_in[0];
    const float* feats    = (const float*)d_in[1];
    const int*   in_rows  = (const int*)  d_in[2];
    const int*   out_rows = (const int*)  d_in[3];
    const float* weight   = (const float*)d_in[4];
    const float* bias     = (const float*)d_in[5];

    const int N = in_sizes[1] / 64;   // feats is [N, 64]
    const int M = in_sizes[2] / 9;    // in_rows is [9, M]

    // d_out is float32: [ float(coords) | out[N,64] ]
    float* outf = (float*)d_out;
    long coords_elems = (long)out_size - (long)N * 64;
    if (coords_elems < 0) coords_elems = 0;
    if (coords_elems > in_sizes[0]) coords_elems = in_sizes[0];
    float* out = outf + coords_elems;

    const int total4 = N * 16;                    // out floats / 4
    const int nc4    = (int)(coords_elems / 4);   // coords: N*3 divisible by 4
    const int tot    = total4 + nc4;
    vsc_prep<<<(tot + 255) / 256, 256>>>(
        (float4*)out, (const float4*)bias, total4,
        (const int4*)coords, (float4*)outf, nc4);

    cudaFuncSetAttribute(vsc_mma, cudaFuncAttributeMaxDynamicSharedMemorySize,
                         SMEM_SZ);
    const int ntiles = (M + TILE_E - 1) / TILE_E;
    dim3 grid(GRID_X, 9);
    vsc_mma<<<grid, 256, SMEM_SZ>>>(feats, in_rows, out_rows, weight, out,
                                    M, ntiles);
}

// round 13
// speedup vs baseline: 1.3118x; 1.0709x over previous
#include <cuda_runtime.h>
#include <cuda_bf16.h>
#include <cstdint>

// VSC3x3Rulebook on GB300 — HMMA bf16-split + TMA bulk-reduce scatter.
// r12 data flow, but the tile loop runs as 4 independent warp-pair pipelines
// (slab-local gather/stage/reduce + 64-thread named barriers, no block syncs).
//   out = scatter_add_{k,m}( feats[in_rows[k,m]] @ weight[k] -> out_rows[k,m] ) + bias
//   d_out (float32): [ float(coords) | out[N,64] ]

#define TILE_E 128
#define GRID_X 32

// dynamic smem layout (16B aligned base; all offsets 16B multiples)
#define WLO_OFF 0          // 64 x 144B  : bf16 W_lo, [co][ci]
#define AHI_OFF 9216       // 128 x 144B : bf16 A_hi
#define ALO_OFF 27648      // 128 x 144B : bf16 A_lo
#define STG_OFF 46080      // 128 x 288B : f32 D stage (72-float stride)
#define SMEM_SZ 82944

// ---- merged prep: bias-init of out + coords int->float cast ----
__global__ void vsc_prep(float4* __restrict__ out4,
                         const float4* __restrict__ bias4, int total4,
                         const int4* __restrict__ coords4,
                         float4* __restrict__ outc4, int nc4) {
    int idx = blockIdx.x * blockDim.x + threadIdx.x;
    if (idx < total4) {
        out4[idx] = bias4[idx & 15];
    } else {
        int j = idx - total4;
        if (j < nc4) {
            int4 v = coords4[j];
            outc4[j] = make_float4((float)v.x, (float)v.y, (float)v.z, (float)v.w);
        }
    }
}

__device__ __forceinline__ uint2 bf16split2(float a, float b) {
    __nv_bfloat16 ha = __float2bfloat16(a);
    __nv_bfloat16 hb = __float2bfloat16(b);
    __nv_bfloat16 la = __float2bfloat16(a - __bfloat162float(ha));
    __nv_bfloat16 lb = __float2bfloat16(b - __bfloat162float(hb));
    uint2 r;
    r.x = (uint32_t)__bfloat16_as_ushort(ha) | ((uint32_t)__bfloat16_as_ushort(hb) << 16);
    r.y = (uint32_t)__bfloat16_as_ushort(la) | ((uint32_t)__bfloat16_as_ushort(lb) << 16);
    return r;
}

__device__ __forceinline__ void mma16816(float* c, const uint32_t* a,
                                         uint32_t b0, uint32_t b1) {
    asm volatile(
        "mma.sync.aligned.m16n8k16.row.col.f32.bf16.bf16.f32 "
        "{%0,%1,%2,%3}, {%4,%5,%6,%7}, {%8,%9}, {%0,%1,%2,%3};"
        : "+f"(c[0]), "+f"(c[1]), "+f"(c[2]), "+f"(c[3])
        : "r"(a[0]), "r"(a[1]), "r"(a[2]), "r"(a[3]), "r"(b0), "r"(b1));
}

#define LDMX4(r, addr)                                                     \
    asm volatile("ldmatrix.sync.aligned.m8n8.x4.shared.b16 "               \
                 "{%0,%1,%2,%3}, [%4];"                                    \
                 : "=r"((r)[0]), "=r"((r)[1]), "=r"((r)[2]), "=r"((r)[3])  \
                 : "r"(addr))
#define LDMX2(r0, r1, addr)                                                \
    asm volatile("ldmatrix.sync.aligned.m8n8.x2.shared.b16 "               \
                 "{%0,%1}, [%2];"                                          \
                 : "=r"(r0), "=r"(r1) : "r"(addr))

#define PAIR_BAR(id)                                                       \
    asm volatile("bar.sync %0, 64;" :: "r"(id) : "memory")

__global__ __launch_bounds__(256, 2) void vsc_mma(
    const float* __restrict__ feats,
    const int*   __restrict__ in_rows,
    const int*   __restrict__ out_rows,
    const float* __restrict__ weight,
    float*       __restrict__ out,
    int M, int ntiles)
{
    extern __shared__ __align__(16) char smem[];
    const uint32_t sb = (uint32_t)__cvta_generic_to_shared(smem);

    const int tid   = threadIdx.x;
    const int w     = tid >> 5;
    const int l     = tid & 31;
    const int eslab = w >> 1;    // 0..3 : 32-entry slab (pair id)
    const int nhalf = w & 1;     // 0/1  : output-column half
    const int k     = blockIdx.y;
    const long kM   = (long)k * M;
    const float* Wg = weight + (size_t)k * 4096;   // [ci][co]

    // ---- W_lo -> smem [co][ci], 144B rows ----
    for (int i = tid; i < 4096; i += 256) {
        const int n = i >> 6, ci = i & 63;
        const float v = Wg[(size_t)ci * 64 + n];
        const float lo = v - __bfloat162float(__float2bfloat16(v));
        *reinterpret_cast<__nv_bfloat16*>(smem + WLO_OFF + n * 144 + ci * 2) =
            __float2bfloat16(lo);
    }

    // ---- W_hi fragments -> registers ----
    uint32_t Bhi[4][4][2];
    {
        const int n = nhalf * 32 + (l >> 2);
        #pragma unroll
        for (int nt = 0; nt < 4; nt++)
            #pragma unroll
            for (int ks = 0; ks < 4; ks++)
                #pragma unroll
                for (int j = 0; j < 2; j++) {
                    const int ci0 = ks * 16 + j * 8 + 2 * (l & 3);
                    const float w0 = Wg[(size_t)ci0 * 64 + n + nt * 8];
                    const float w1 = Wg[(size_t)(ci0 + 1) * 64 + n + nt * 8];
                    Bhi[nt][ks][j] =
                        (uint32_t)__bfloat16_as_ushort(__float2bfloat16(w0))
                      | ((uint32_t)__bfloat16_as_ushort(__float2bfloat16(w1)) << 16);
                }
    }
    __syncthreads();   // W_lo visible to all; only block-wide sync in kernel

    const uint32_t a_row = (l & 7) + ((l >> 3) & 1) * 8;
    const uint32_t a_kof = (l >> 4) * 8;
    const uint32_t b_row = nhalf * 32 + (l & 7);
    const uint32_t b_kof = ((l >> 3) & 1) * 8;

    // pair-local gather striping: 64 threads cover 32 entries x 8 octets
    const int pt  = (nhalf << 5) | l;   // 0..63 within pair
    const int er2 = pt >> 3;            // 0..7
    const int g8  = pt & 7;             // ci octet
    const int bar = eslab + 1;          // named barrier id 1..4

    for (int tile = blockIdx.x; tile < ntiles; tile += GRID_X) {
        const int ebase = tile * TILE_E;

        // out row for this pair's reduce (even warp, lane l -> entry)
        int orw = -1;
        if (nhalf == 0) {
            const int eg = ebase + eslab * 32 + l;
            if (eg < M) orw = __ldg(out_rows + kM + eg);
        }

        // ---- gather + split + STS (own slab rows only) ----
        #pragma unroll
        for (int p = 0; p < 4; p++) {
            const int e = eslab * 32 + p * 8 + er2;
            int eg = ebase + e;
            if (eg >= M) eg = M - 1;
            const int irow = __ldg(in_rows + kM + eg);
            const float4* fp = reinterpret_cast<const float4*>(
                feats + (size_t)irow * 64 + g8 * 8);
            const float4 v0 = __ldg(fp);
            const float4 v1 = __ldg(fp + 1);
            const uint2 p0 = bf16split2(v0.x, v0.y);
            const uint2 p1 = bf16split2(v0.z, v0.w);
            const uint2 p2 = bf16split2(v1.x, v1.y);
            const uint2 p3 = bf16split2(v1.z, v1.w);
            const int off = e * 144 + g8 * 16;
            *reinterpret_cast<uint4*>(smem + AHI_OFF + off) =
                make_uint4(p0.x, p1.x, p2.x, p3.x);
            *reinterpret_cast<uint4*>(smem + ALO_OFF + off) =
                make_uint4(p0.y, p1.y, p2.y, p3.y);
        }
        PAIR_BAR(bar);   // slab's A rows ready for both warps of the pair

        // ---- compute (reads only own slab's A rows + shared W) ----
        float acc[2][4][4];
        #pragma unroll
        for (int s = 0; s < 2; s++)
            #pragma unroll
            for (int nt = 0; nt < 4; nt++)
                #pragma unroll
                for (int r = 0; r < 4; r++) acc[s][nt][r] = 0.f;

        #pragma unroll
        for (int ks = 0; ks < 4; ks++) {
            uint32_t blo[4][2];
            #pragma unroll
            for (int nt = 0; nt < 4; nt++) {
                const uint32_t ba = sb + WLO_OFF
                    + (b_row + nt * 8) * 144 + (ks * 16 + b_kof) * 2;
                LDMX2(blo[nt][0], blo[nt][1], ba);
            }
            #pragma unroll
            for (int s = 0; s < 2; s++) {
                const uint32_t ao =
                    (eslab * 32 + s * 16 + a_row) * 144 + (ks * 16 + a_kof) * 2;
                uint32_t ahi[4], alo[4];
                LDMX4(ahi, sb + AHI_OFF + ao);
                LDMX4(alo, sb + ALO_OFF + ao);
                #pragma unroll
                for (int nt = 0; nt < 4; nt++) {
                    mma16816(acc[s][nt], ahi, Bhi[nt][ks][0], Bhi[nt][ks][1]);
                    mma16816(acc[s][nt], ahi, blo[nt][0],     blo[nt][1]);
                    mma16816(acc[s][nt], alo, Bhi[nt][ks][0], Bhi[nt][ks][1]);
                }
            }
        }

        // ---- epilogue (pair-scoped) ----
        // even warp owns the TMA reduce chain: its previous group must have
        // READ the slab's stage rows before the pair overwrites them.
        if (nhalf == 0)
            asm volatile("cp.async.bulk.wait_group.read 0;" ::: "memory");
        PAIR_BAR(bar);   // stage rows free; both warps past ldmatrix

        {
            const int r0 = l >> 2;            // 0..7
            const int cb = 2 * (l & 3);       // 0,2,4,6
            float* stg = reinterpret_cast<float*>(smem + STG_OFF);
            #pragma unroll
            for (int s = 0; s < 2; s++) {
                const int eb = eslab * 32 + s * 16;
                #pragma unroll
                for (int nt = 0; nt < 4; nt++) {
                    const int c = nhalf * 32 + nt * 8 + cb;
                    *reinterpret_cast<float2*>(&stg[(eb + r0) * 72 + c]) =
                        make_float2(acc[s][nt][0], acc[s][nt][1]);
                    *reinterpret_cast<float2*>(&stg[(eb + r0 + 8) * 72 + c]) =
                        make_float2(acc[s][nt][2], acc[s][nt][3]);
                }
            }
        }
        asm volatile("fence.proxy.async.shared::cta;" ::: "memory");
        PAIR_BAR(bar);   // slab's stage rows visible to async proxy

        if (nhalf == 0) {
            if (orw >= 0) {
                const int e = eslab * 32 + l;
                const float* dst = out + (size_t)orw * 64;
                const uint32_t src = sb + STG_OFF + e * 288;
                asm volatile(
                    "cp.reduce.async.bulk.global.shared::cta.bulk_group.add.f32 "
                    "[%0], [%1], 256;"
                    :: "l"(dst), "r"(src) : "memory");
            }
            asm volatile("cp.async.bulk.commit_group;" ::: "memory");
        }
        // next gather writes only this slab's A rows; both warps are past the
        // last pair barrier, so their ldmatrix reads of tile t are complete.
    }

    if (nhalf == 0)
        asm volatile("cp.async.bulk.wait_group 0;" ::: "memory");
}

extern "C" void kernel_launch(void* const* d_in, const int* in_sizes, int n_in,
                              void* d_out, int out_size) {
    const int*   coords   = (const int*)  d_in[0];
    const float* feats    = (const float*)d_in[1];
    const int*   in_rows  = (const int*)  d_in[2];
    const int*   out_rows = (const int*)  d_in[3];
    const float* weight   = (const float*)d_in[4];
    const float* bias     = (const float*)d_in[5];

    const int N = in_sizes[1] / 64;   // feats is [N, 64]
    const int M = in_sizes[2] / 9;    // in_rows is [9, M]

    // d_out is float32: [ float(coords) | out[N,64] ]
    float* outf = (float*)d_out;
    long coords_elems = (long)out_size - (long)N * 64;
    if (coords_elems < 0) coords_elems = 0;
    if (coords_elems > in_sizes[0]) coords_elems = in_sizes[0];
    float* out = outf + coords_elems;

    const int total4 = N * 16;                    // out floats / 4
    const int nc4    = (int)(coords_elems / 4);   // coords: N*3 divisible by 4
    const int tot    = total4 + nc4;
    vsc_prep<<<(tot + 255) / 256, 256>>>(
        (float4*)out, (const float4*)bias, total4,
        (const int4*)coords, (float4*)outf, nc4);

    cudaFuncSetAttribute(vsc_mma, cudaFuncAttributeMaxDynamicSharedMemorySize,
                         SMEM_SZ);
    const int ntiles = (M + TILE_E - 1) / TILE_E;
    dim3 grid(GRID_X, 9);
    vsc_mma<<<grid, 256, SMEM_SZ>>>(feats, in_rows, out_rows, weight, out,
                                    M, ntiles);
}

// round 14
// speedup vs baseline: 1.3993x; 1.0667x over previous
#include <cuda_runtime.h>
#include <cuda_bf16.h>
#include <cstdint>

// VSC3x3Rulebook on GB300 — HMMA bf16-split + TMA bulk-reduce scatter.
// r13 pipeline (4 warp-pair pipelines, named barriers) + truncation-based
// fast bf16 split + reduce issuance split across both warps of a pair.
//   out = scatter_add_{k,m}( feats[in_rows[k,m]] @ weight[k] -> out_rows[k,m] ) + bias
//   d_out (float32): [ float(coords) | out[N,64] ]

#define TILE_E 128
#define GRID_X 32

// dynamic smem layout (16B aligned base; all offsets 16B multiples)
#define WLO_OFF 0          // 64 x 144B  : bf16 W_lo, [co][ci]
#define AHI_OFF 9216       // 128 x 144B : bf16 A_hi
#define ALO_OFF 27648      // 128 x 144B : bf16 A_lo
#define STG_OFF 46080      // 128 x 288B : f32 D stage (72-float stride)
#define SMEM_SZ 82944

// ---- merged prep: bias-init of out + coords int->float cast ----
__global__ void vsc_prep(float4* __restrict__ out4,
                         const float4* __restrict__ bias4, int total4,
                         const int4* __restrict__ coords4,
                         float4* __restrict__ outc4, int nc4) {
    int idx = blockIdx.x * blockDim.x + threadIdx.x;
    if (idx < total4) {
        out4[idx] = bias4[idx & 15];
    } else {
        int j = idx - total4;
        if (j < nc4) {
            int4 v = coords4[j];
            outc4[j] = make_float4((float)v.x, (float)v.y, (float)v.z, (float)v.w);
        }
    }
}

// Truncation split: hi = a with low 16 bits cleared (exact bf16),
// lo = rn_bf16(a - hi). r.x packs {hi(b),hi(a)}, r.y packs {lo(b),lo(a)}.
__device__ __forceinline__ uint2 bf16split2(float a, float b) {
    const uint32_t ua = __float_as_uint(a), ub = __float_as_uint(b);
    uint2 r;
    asm("prmt.b32 %0, %1, %2, 0x7632;" : "=r"(r.x) : "r"(ua), "r"(ub));
    const float ha = __uint_as_float(ua & 0xFFFF0000u);
    const float hb = __uint_as_float(ub & 0xFFFF0000u);
    const float la = a - ha, lb = b - hb;
    asm("cvt.rn.bf16x2.f32 %0, %1, %2;" : "=r"(r.y) : "f"(lb), "f"(la));
    return r;
}

__device__ __forceinline__ void mma16816(float* c, const uint32_t* a,
                                         uint32_t b0, uint32_t b1) {
    asm volatile(
        "mma.sync.aligned.m16n8k16.row.col.f32.bf16.bf16.f32 "
        "{%0,%1,%2,%3}, {%4,%5,%6,%7}, {%8,%9}, {%0,%1,%2,%3};"
        : "+f"(c[0]), "+f"(c[1]), "+f"(c[2]), "+f"(c[3])
        : "r"(a[0]), "r"(a[1]), "r"(a[2]), "r"(a[3]), "r"(b0), "r"(b1));
}

#define LDMX4(r, addr)                                                     \
    asm volatile("ldmatrix.sync.aligned.m8n8.x4.shared.b16 "               \
                 "{%0,%1,%2,%3}, [%4];"                                    \
                 : "=r"((r)[0]), "=r"((r)[1]), "=r"((r)[2]), "=r"((r)[3])  \
                 : "r"(addr))
#define LDMX2(r0, r1, addr)                                                \
    asm volatile("ldmatrix.sync.aligned.m8n8.x2.shared.b16 "               \
                 "{%0,%1}, [%2];"                                          \
                 : "=r"(r0), "=r"(r1) : "r"(addr))

#define PAIR_BAR(id)                                                       \
    asm volatile("bar.sync %0, 64;" :: "r"(id) : "memory")

__global__ __launch_bounds__(256, 2) void vsc_mma(
    const float* __restrict__ feats,
    const int*   __restrict__ in_rows,
    const int*   __restrict__ out_rows,
    const float* __restrict__ weight,
    float*       __restrict__ out,
    int M, int ntiles)
{
    extern __shared__ __align__(16) char smem[];
    const uint32_t sb = (uint32_t)__cvta_generic_to_shared(smem);

    const int tid   = threadIdx.x;
    const int w     = tid >> 5;
    const int l     = tid & 31;
    const int eslab = w >> 1;    // 0..3 : 32-entry slab (pair id)
    const int nhalf = w & 1;     // 0/1  : output-column half
    const int k     = blockIdx.y;
    const long kM   = (long)k * M;
    const float* Wg = weight + (size_t)k * 4096;   // [ci][co]

    // ---- W_lo -> smem [co][ci], 144B rows (rn split for W, done once) ----
    for (int i = tid; i < 4096; i += 256) {
        const int n = i >> 6, ci = i & 63;
        const float v = Wg[(size_t)ci * 64 + n];
        const float lo = v - __bfloat162float(__float2bfloat16(v));
        *reinterpret_cast<__nv_bfloat16*>(smem + WLO_OFF + n * 144 + ci * 2) =
            __float2bfloat16(lo);
    }

    // ---- W_hi fragments -> registers ----
    uint32_t Bhi[4][4][2];
    {
        const int n = nhalf * 32 + (l >> 2);
        #pragma unroll
        for (int nt = 0; nt < 4; nt++)
            #pragma unroll
            for (int ks = 0; ks < 4; ks++)
                #pragma unroll
                for (int j = 0; j < 2; j++) {
                    const int ci0 = ks * 16 + j * 8 + 2 * (l & 3);
                    const float w0 = Wg[(size_t)ci0 * 64 + n + nt * 8];
                    const float w1 = Wg[(size_t)(ci0 + 1) * 64 + n + nt * 8];
                    Bhi[nt][ks][j] =
                        (uint32_t)__bfloat16_as_ushort(__float2bfloat16(w0))
                      | ((uint32_t)__bfloat16_as_ushort(__float2bfloat16(w1)) << 16);
                }
    }
    __syncthreads();   // W_lo visible to all; only block-wide sync in kernel

    const uint32_t a_row = (l & 7) + ((l >> 3) & 1) * 8;
    const uint32_t a_kof = (l >> 4) * 8;
    const uint32_t b_row = nhalf * 32 + (l & 7);
    const uint32_t b_kof = ((l >> 3) & 1) * 8;

    // pair-local gather striping: 64 threads cover 32 entries x 8 octets
    const int pt  = (nhalf << 5) | l;   // 0..63 within pair
    const int er2 = pt >> 3;            // 0..7
    const int g8  = pt & 7;             // ci octet
    const int bar = eslab + 1;          // named barrier id 1..4

    for (int tile = blockIdx.x; tile < ntiles; tile += GRID_X) {
        const int ebase = tile * TILE_E;

        // each warp of the pair owns 16 reduce entries (lanes 0..15)
        int orw = -1;
        if (l < 16) {
            const int eg = ebase + eslab * 32 + nhalf * 16 + l;
            if (eg < M) orw = __ldg(out_rows + kM + eg);
        }

        // ---- gather + split + STS (own slab rows only) ----
        #pragma unroll
        for (int p = 0; p < 4; p++) {
            const int e = eslab * 32 + p * 8 + er2;
            int eg = ebase + e;
            if (eg >= M) eg = M - 1;
            const int irow = __ldg(in_rows + kM + eg);
            const float4* fp = reinterpret_cast<const float4*>(
                feats + (size_t)irow * 64 + g8 * 8);
            const float4 v0 = __ldg(fp);
            const float4 v1 = __ldg(fp + 1);
            const uint2 p0 = bf16split2(v0.x, v0.y);
            const uint2 p1 = bf16split2(v0.z, v0.w);
            const uint2 p2 = bf16split2(v1.x, v1.y);
            const uint2 p3 = bf16split2(v1.z, v1.w);
            const int off = e * 144 + g8 * 16;
            *reinterpret_cast<uint4*>(smem + AHI_OFF + off) =
                make_uint4(p0.x, p1.x, p2.x, p3.x);
            *reinterpret_cast<uint4*>(smem + ALO_OFF + off) =
                make_uint4(p0.y, p1.y, p2.y, p3.y);
        }
        PAIR_BAR(bar);   // slab's A rows ready for both warps of the pair

        // ---- compute (reads only own slab's A rows + shared W) ----
        float acc[2][4][4];
        #pragma unroll
        for (int s = 0; s < 2; s++)
            #pragma unroll
            for (int nt = 0; nt < 4; nt++)
                #pragma unroll
                for (int r = 0; r < 4; r++) acc[s][nt][r] = 0.f;

        #pragma unroll
        for (int ks = 0; ks < 4; ks++) {
            uint32_t blo[4][2];
            #pragma unroll
            for (int nt = 0; nt < 4; nt++) {
                const uint32_t ba = sb + WLO_OFF
                    + (b_row + nt * 8) * 144 + (ks * 16 + b_kof) * 2;
                LDMX2(blo[nt][0], blo[nt][1], ba);
            }
            #pragma unroll
            for (int s = 0; s < 2; s++) {
                const uint32_t ao =
                    (eslab * 32 + s * 16 + a_row) * 144 + (ks * 16 + a_kof) * 2;
                uint32_t ahi[4], alo[4];
                LDMX4(ahi, sb + AHI_OFF + ao);
                LDMX4(alo, sb + ALO_OFF + ao);
                #pragma unroll
                for (int nt = 0; nt < 4; nt++) {
                    mma16816(acc[s][nt], ahi, Bhi[nt][ks][0], Bhi[nt][ks][1]);
                    mma16816(acc[s][nt], ahi, blo[nt][0],     blo[nt][1]);
                    mma16816(acc[s][nt], alo, Bhi[nt][ks][0], Bhi[nt][ks][1]);
                }
            }
        }

        // ---- epilogue (pair-scoped) ----
        // each warp owns its own reduce chain: previous groups must have READ
        // the slab's stage rows before the pair overwrites them.
        asm volatile("cp.async.bulk.wait_group.read 0;" ::: "memory");
        PAIR_BAR(bar);   // stage rows free; both warps past ldmatrix

        {
            const int r0 = l >> 2;            // 0..7
            const int cb = 2 * (l & 3);       // 0,2,4,6
            float* stg = reinterpret_cast<float*>(smem + STG_OFF);
            #pragma unroll
            for (int s = 0; s < 2; s++) {
                const int eb = eslab * 32 + s * 16;
                #pragma unroll
                for (int nt = 0; nt < 4; nt++) {
                    const int c = nhalf * 32 + nt * 8 + cb;
                    *reinterpret_cast<float2*>(&stg[(eb + r0) * 72 + c]) =
                        make_float2(acc[s][nt][0], acc[s][nt][1]);
                    *reinterpret_cast<float2*>(&stg[(eb + r0 + 8) * 72 + c]) =
                        make_float2(acc[s][nt][2], acc[s][nt][3]);
                }
            }
        }
        asm volatile("fence.proxy.async.shared::cta;" ::: "memory");
        PAIR_BAR(bar);   // slab's stage rows visible to async proxy

        if (orw >= 0) {
            const int e = eslab * 32 + nhalf * 16 + l;
            const float* dst = out + (size_t)orw * 64;
            const uint32_t src = sb + STG_OFF + e * 288;
            asm volatile(
                "cp.reduce.async.bulk.global.shared::cta.bulk_group.add.f32 "
                "[%0], [%1], 256;"
                :: "l"(dst), "r"(src) : "memory");
        }
        asm volatile("cp.async.bulk.commit_group;" ::: "memory");
        // next gather writes only this slab's A rows; both warps are past the
        // last pair barrier, so their ldmatrix reads of tile t are complete.
    }

    asm volatile("cp.async.bulk.wait_group 0;" ::: "memory");
}

extern "C" void kernel_launch(void* const* d_in, const int* in_sizes, int n_in,
                              void* d_out, int out_size) {
    const int*   coords   = (const int*)  d_in[0];
    const float* feats    = (const float*)d_in[1];
    const int*   in_rows  = (const int*)  d_in[2];
    const int*   out_rows = (const int*)  d_in[3];
    const float* weight   = (const float*)d_in[4];
    const float* bias     = (const float*)d_in[5];

    const int N = in_sizes[1] / 64;   // feats is [N, 64]
    const int M = in_sizes[2] / 9;    // in_rows is [9, M]

    // d_out is float32: [ float(coords) | out[N,64] ]
    float* outf = (float*)d_out;
    long coords_elems = (long)out_size - (long)N * 64;
    if (coords_elems < 0) coords_elems = 0;
    if (coords_elems > in_sizes[0]) coords_elems = in_sizes[0];
    float* out = outf + coords_elems;

    const int total4 = N * 16;                    // out floats / 4
    const int nc4    = (int)(coords_elems / 4);   // coords: N*3 divisible by 4
    const int tot    = total4 + nc4;
    vsc_prep<<<(tot + 255) / 256, 256>>>(
        (float4*)out, (const float4*)bias, total4,
        (const int4*)coords, (float4*)outf, nc4);

    cudaFuncSetAttribute(vsc_mma, cudaFuncAttributeMaxDynamicSharedMemorySize,
                         SMEM_SZ);
    const int ntiles = (M + TILE_E - 1) / TILE_E;
    dim3 grid(GRID_X, 9);
    vsc_mma<<<grid, 256, SMEM_SZ>>>(feats, in_rows, out_rows, weight, out,
                                    M, ntiles);
}

// round 15
// speedup vs baseline: 1.4533x; 1.0386x over previous
#include <cuda_runtime.h>
#include <cuda_bf16.h>
#include <cstdint>

// VSC3x3Rulebook on GB300 — HMMA bf16-split + TMA bulk-reduce scatter.
// r14 pipeline (4 warp-pair pipelines, named barriers, truncation A-split,
// split reduce issuance) + W hi AND lo register-resident (no W smem reads),
// accumulator halved via sequential s-tiles.
//   out = scatter_add_{k,m}( feats[in_rows[k,m]] @ weight[k] -> out_rows[k,m] ) + bias
//   d_out (float32): [ float(coords) | out[N,64] ]

#define TILE_E 128
#define GRID_X 32

// dynamic smem layout (16B aligned base)
#define AHI_OFF 0          // 128 x 144B : bf16 A_hi
#define ALO_OFF 18432      // 128 x 144B : bf16 A_lo
#define STG_OFF 36864      // 128 x 288B : f32 D stage (72-float stride)
#define SMEM_SZ 73728

// ---- merged prep: bias-init of out + coords int->float cast ----
__global__ void vsc_prep(float4* __restrict__ out4,
                         const float4* __restrict__ bias4, int total4,
                         const int4* __restrict__ coords4,
                         float4* __restrict__ outc4, int nc4) {
    int idx = blockIdx.x * blockDim.x + threadIdx.x;
    if (idx < total4) {
        out4[idx] = bias4[idx & 15];
    } else {
        int j = idx - total4;
        if (j < nc4) {
            int4 v = coords4[j];
            outc4[j] = make_float4((float)v.x, (float)v.y, (float)v.z, (float)v.w);
        }
    }
}

// Truncation split: hi = a with low 16 bits cleared (exact bf16),
// lo = rn_bf16(a - hi). r.x packs {hi(b),hi(a)}, r.y packs {lo(b),lo(a)}.
__device__ __forceinline__ uint2 bf16split2(float a, float b) {
    const uint32_t ua = __float_as_uint(a), ub = __float_as_uint(b);
    uint2 r;
    asm("prmt.b32 %0, %1, %2, 0x7632;" : "=r"(r.x) : "r"(ua), "r"(ub));
    const float ha = __uint_as_float(ua & 0xFFFF0000u);
    const float hb = __uint_as_float(ub & 0xFFFF0000u);
    const float la = a - ha, lb = b - hb;
    asm("cvt.rn.bf16x2.f32 %0, %1, %2;" : "=r"(r.y) : "f"(lb), "f"(la));
    return r;
}

__device__ __forceinline__ void mma16816(float* c, const uint32_t* a,
                                         uint32_t b0, uint32_t b1) {
    asm volatile(
        "mma.sync.aligned.m16n8k16.row.col.f32.bf16.bf16.f32 "
        "{%0,%1,%2,%3}, {%4,%5,%6,%7}, {%8,%9}, {%0,%1,%2,%3};"
        : "+f"(c[0]), "+f"(c[1]), "+f"(c[2]), "+f"(c[3])
        : "r"(a[0]), "r"(a[1]), "r"(a[2]), "r"(a[3]), "r"(b0), "r"(b1));
}

#define LDMX4(r, addr)                                                     \
    asm volatile("ldmatrix.sync.aligned.m8n8.x4.shared.b16 "               \
                 "{%0,%1,%2,%3}, [%4];"                                    \
                 : "=r"((r)[0]), "=r"((r)[1]), "=r"((r)[2]), "=r"((r)[3])  \
                 : "r"(addr))

#define PAIR_BAR(id)                                                       \
    asm volatile("bar.sync %0, 64;" :: "r"(id) : "memory")

__global__ __launch_bounds__(256, 2) void vsc_mma(
    const float* __restrict__ feats,
    const int*   __restrict__ in_rows,
    const int*   __restrict__ out_rows,
    const float* __restrict__ weight,
    float*       __restrict__ out,
    int M, int ntiles)
{
    extern __shared__ __align__(16) char smem[];
    const uint32_t sb = (uint32_t)__cvta_generic_to_shared(smem);

    const int tid   = threadIdx.x;
    const int w     = tid >> 5;
    const int l     = tid & 31;
    const int eslab = w >> 1;    // 0..3 : 32-entry slab (pair id)
    const int nhalf = w & 1;     // 0/1  : output-column half
    const int k     = blockIdx.y;
    const long kM   = (long)k * M;
    const float* Wg = weight + (size_t)k * 4096;   // [ci][co]

    // ---- W_hi AND W_lo fragments -> registers (64 regs) ----
    uint32_t Bhi[4][4][2], Blo[4][4][2];
    {
        const int n = nhalf * 32 + (l >> 2);
        #pragma unroll
        for (int nt = 0; nt < 4; nt++)
            #pragma unroll
            for (int ks = 0; ks < 4; ks++)
                #pragma unroll
                for (int j = 0; j < 2; j++) {
                    const int ci0 = ks * 16 + j * 8 + 2 * (l & 3);
                    const float w0 = Wg[(size_t)ci0 * 64 + n + nt * 8];
                    const float w1 = Wg[(size_t)(ci0 + 1) * 64 + n + nt * 8];
                    const __nv_bfloat16 h0 = __float2bfloat16(w0);
                    const __nv_bfloat16 h1 = __float2bfloat16(w1);
                    Bhi[nt][ks][j] =
                        (uint32_t)__bfloat16_as_ushort(h0)
                      | ((uint32_t)__bfloat16_as_ushort(h1) << 16);
                    const float l0 = w0 - __bfloat162float(h0);
                    const float l1 = w1 - __bfloat162float(h1);
                    Blo[nt][ks][j] =
                        (uint32_t)__bfloat16_as_ushort(__float2bfloat16(l0))
                      | ((uint32_t)__bfloat16_as_ushort(__float2bfloat16(l1)) << 16);
                }
    }

    const uint32_t a_row = (l & 7) + ((l >> 3) & 1) * 8;
    const uint32_t a_kof = (l >> 4) * 8;

    // pair-local gather striping: 64 threads cover 32 entries x 8 octets
    const int pt  = (nhalf << 5) | l;   // 0..63 within pair
    const int er2 = pt >> 3;            // 0..7
    const int g8  = pt & 7;             // ci octet
    const int bar = eslab + 1;          // named barrier id 1..4

    for (int tile = blockIdx.x; tile < ntiles; tile += GRID_X) {
        const int ebase = tile * TILE_E;

        // each warp of the pair owns 16 reduce entries (lanes 0..15)
        int orw = -1;
        if (l < 16) {
            const int eg = ebase + eslab * 32 + nhalf * 16 + l;
            if (eg < M) orw = __ldg(out_rows + kM + eg);
        }

        // ---- gather + split + STS (own slab rows only) ----
        #pragma unroll
        for (int p = 0; p < 4; p++) {
            const int e = eslab * 32 + p * 8 + er2;
            int eg = ebase + e;
            if (eg >= M) eg = M - 1;
            const int irow = __ldg(in_rows + kM + eg);
            const float4* fp = reinterpret_cast<const float4*>(
                feats + (size_t)irow * 64 + g8 * 8);
            const float4 v0 = __ldg(fp);
            const float4 v1 = __ldg(fp + 1);
            const uint2 p0 = bf16split2(v0.x, v0.y);
            const uint2 p1 = bf16split2(v0.z, v0.w);
            const uint2 p2 = bf16split2(v1.x, v1.y);
            const uint2 p3 = bf16split2(v1.z, v1.w);
            const int off = e * 144 + g8 * 16;
            *reinterpret_cast<uint4*>(smem + AHI_OFF + off) =
                make_uint4(p0.x, p1.x, p2.x, p3.x);
            *reinterpret_cast<uint4*>(smem + ALO_OFF + off) =
                make_uint4(p0.y, p1.y, p2.y, p3.y);
        }
        PAIR_BAR(bar);   // slab's A rows ready for both warps of the pair

        float acc[4][4];
        float* stg = reinterpret_cast<float*>(smem + STG_OFF);
        const int r0 = l >> 2;            // 0..7
        const int cb = 2 * (l & 3);       // 0,2,4,6

        // ---- compute s = 0 (rows eslab*32 .. +15) ----
        #pragma unroll
        for (int nt = 0; nt < 4; nt++)
            #pragma unroll
            for (int r = 0; r < 4; r++) acc[nt][r] = 0.f;
        #pragma unroll
        for (int ks = 0; ks < 4; ks++) {
            const uint32_t ao =
                (eslab * 32 + a_row) * 144 + (ks * 16 + a_kof) * 2;
            uint32_t ahi[4], alo[4];
            LDMX4(ahi, sb + AHI_OFF + ao);
            LDMX4(alo, sb + ALO_OFF + ao);
            #pragma unroll
            for (int nt = 0; nt < 4; nt++) {
                mma16816(acc[nt], ahi, Bhi[nt][ks][0], Bhi[nt][ks][1]);
                mma16816(acc[nt], ahi, Blo[nt][ks][0], Blo[nt][ks][1]);
                mma16816(acc[nt], alo, Bhi[nt][ks][0], Bhi[nt][ks][1]);
            }
        }

        // previous reduce groups must have READ the slab's stage rows
        asm volatile("cp.async.bulk.wait_group.read 0;" ::: "memory");
        PAIR_BAR(bar);   // stage rows free for both warps

        // ---- stage s = 0 ----
        {
            const int eb = eslab * 32;
            #pragma unroll
            for (int nt = 0; nt < 4; nt++) {
                const int c = nhalf * 32 + nt * 8 + cb;
                *reinterpret_cast<float2*>(&stg[(eb + r0) * 72 + c]) =
                    make_float2(acc[nt][0], acc[nt][1]);
                *reinterpret_cast<float2*>(&stg[(eb + r0 + 8) * 72 + c]) =
                    make_float2(acc[nt][2], acc[nt][3]);
            }
        }

        // ---- compute s = 1 (rows eslab*32+16 .. +31), reuse acc ----
        #pragma unroll
        for (int nt = 0; nt < 4; nt++)
            #pragma unroll
            for (int r = 0; r < 4; r++) acc[nt][r] = 0.f;
        #pragma unroll
        for (int ks = 0; ks < 4; ks++) {
            const uint32_t ao =
                (eslab * 32 + 16 + a_row) * 144 + (ks * 16 + a_kof) * 2;
            uint32_t ahi[4], alo[4];
            LDMX4(ahi, sb + AHI_OFF + ao);
            LDMX4(alo, sb + ALO_OFF + ao);
            #pragma unroll
            for (int nt = 0; nt < 4; nt++) {
                mma16816(acc[nt], ahi, Bhi[nt][ks][0], Bhi[nt][ks][1]);
                mma16816(acc[nt], ahi, Blo[nt][ks][0], Blo[nt][ks][1]);
                mma16816(acc[nt], alo, Bhi[nt][ks][0], Bhi[nt][ks][1]);
            }
        }

        // ---- stage s = 1 ----
        {
            const int eb = eslab * 32 + 16;
            #pragma unroll
            for (int nt = 0; nt < 4; nt++) {
                const int c = nhalf * 32 + nt * 8 + cb;
                *reinterpret_cast<float2*>(&stg[(eb + r0) * 72 + c]) =
                    make_float2(acc[nt][0], acc[nt][1]);
                *reinterpret_cast<float2*>(&stg[(eb + r0 + 8) * 72 + c]) =
                    make_float2(acc[nt][2], acc[nt][3]);
            }
        }
        asm volatile("fence.proxy.async.shared::cta;" ::: "memory");
        PAIR_BAR(bar);   // all stage writes + all ldmatrix of this tile done

        if (orw >= 0) {
            const int e = eslab * 32 + nhalf * 16 + l;
            const float* dst = out + (size_t)orw * 64;
            const uint32_t src = sb + STG_OFF + e * 288;
            asm volatile(
                "cp.reduce.async.bulk.global.shared::cta.bulk_group.add.f32 "
                "[%0], [%1], 256;"
                :: "l"(dst), "r"(src) : "memory");
        }
        asm volatile("cp.async.bulk.commit_group;" ::: "memory");
        // next gather overwrites this slab's A rows: safe, all warps are past
        // the last pair barrier (and thus past all ldmatrix reads of tile t).
    }

    asm volatile("cp.async.bulk.wait_group 0;" ::: "memory");
}

extern "C" void kernel_launch(void* const* d_in, const int* in_sizes, int n_in,
                              void* d_out, int out_size) {
    const int*   coords   = (const int*)  d_in[0];
    const float* feats    = (const float*)d_in[1];
    const int*   in_rows  = (const int*)  d_in[2];
    const int*   out_rows = (const int*)  d_in[3];
    const float* weight   = (const float*)d_in[4];
    const float* bias     = (const float*)d_in[5];

    const int N = in_sizes[1] / 64;   // feats is [N, 64]
    const int M = in_sizes[2] / 9;    // in_rows is [9, M]

    // d_out is float32: [ float(coords) | out[N,64] ]
    float* outf = (float*)d_out;
    long coords_elems = (long)out_size - (long)N * 64;
    if (coords_elems < 0) coords_elems = 0;
    if (coords_elems > in_sizes[0]) coords_elems = in_sizes[0];
    float* out = outf + coords_elems;

    const int total4 = N * 16;                    // out floats / 4
    const int nc4    = (int)(coords_elems / 4);   // coords: N*3 divisible by 4
    const int tot    = total4 + nc4;
    vsc_prep<<<(tot + 255) / 256, 256>>>(
        (float4*)out, (const float4*)bias, total4,
        (const int4*)coords, (float4*)outf, nc4);

    cudaFuncSetAttribute(vsc_mma, cudaFuncAttributeMaxDynamicSharedMemorySize,
                         SMEM_SZ);
    const int ntiles = (M + TILE_E - 1) / TILE_E;
    dim3 grid(GRID_X, 9);
    vsc_mma<<<grid, 256, SMEM_SZ>>>(feats, in_rows, out_rows, weight, out,
                                    M, ntiles);
}